// round 4
// baseline (speedup 1.0000x reference)
#include <cuda_runtime.h>
#include <cstdint>

#define BSZ   4
#define CD    32
#define HD    1024
#define WD    64
#define NHEAD 8

#define BQ 64
#define BK 64

// Scratch: q, k, v, line in [B, W, H, C] layout (per-(b,w) contiguous [H,C] matrices)
#define ELEMS (BSZ * WD * HD * CD)   // 8,388,608
__device__ float g_q[ELEMS];
__device__ float g_k[ELEMS];
__device__ float g_v[ELEMS];
__device__ float g_line[ELEMS];

// ---------------------------------------------------------------------------
// Kernel 1: fused QKV 1x1-conv projection.
// out[b,o,h,w] = sum_c x[b,c,h,w] * W[o,c] + bias[o], written transposed to
// [B,W,H,C] scratch. One thread per (b,h,w) position; weights in SMEM
// (broadcast reads). Adjacent threads -> adjacent w -> coalesced x loads.
// ---------------------------------------------------------------------------
__global__ __launch_bounds__(256) void qkv_proj(
    const float* __restrict__ x,
    const float* __restrict__ wq, const float* __restrict__ bq,
    const float* __restrict__ wk, const float* __restrict__ bk,
    const float* __restrict__ wv, const float* __restrict__ bv)
{
    __shared__ float shw[3][32][32];
    __shared__ float shb[3][32];
    int tid = threadIdx.x;
    for (int i = tid; i < 3 * 1024; i += 256) {
        int m = i >> 10, r = i & 1023;
        const float* ws = (m == 0) ? wq : ((m == 1) ? wk : wv);
        shw[m][r >> 5][r & 31] = ws[r];
    }
    if (tid < 96) {
        int m = tid >> 5, o = tid & 31;
        const float* bs = (m == 0) ? bq : ((m == 1) ? bk : bv);
        shb[m][o] = bs[o];
    }
    __syncthreads();

    int p = blockIdx.x * 256 + tid;         // 0 .. B*H*W-1
    int w = p & (WD - 1);
    int h = (p >> 6) & (HD - 1);
    int b = p >> 16;

    float xv[32];
    const float* xp = x + (size_t)b * CD * HD * WD + (size_t)h * WD + w;
#pragma unroll
    for (int c = 0; c < 32; c++) xv[c] = xp[(size_t)c * HD * WD];

    size_t obase = (((size_t)b * WD + w) * HD + h) * CD;

#pragma unroll 1
    for (int o4 = 0; o4 < 32; o4 += 4) {
        float aq[4], ak[4], av[4];
#pragma unroll
        for (int u = 0; u < 4; u++) {
            aq[u] = shb[0][o4 + u];
            ak[u] = shb[1][o4 + u];
            av[u] = shb[2][o4 + u];
        }
#pragma unroll
        for (int c = 0; c < 32; c++) {
            float xc = xv[c];
#pragma unroll
            for (int u = 0; u < 4; u++) {
                aq[u] += xc * shw[0][o4 + u][c];
                ak[u] += xc * shw[1][o4 + u][c];
                av[u] += xc * shw[2][o4 + u][c];
            }
        }
        *(float4*)&g_q[obase + o4] = make_float4(aq[0], aq[1], aq[2], aq[3]);
        *(float4*)&g_k[obase + o4] = make_float4(ak[0], ak[1], ak[2], ak[3]);
        *(float4*)&g_v[obase + o4] = make_float4(av[0], av[1], av[2], av[3]);
    }
}

// ---------------------------------------------------------------------------
// Kernel 2: attention per (b,w). Block = 64-query tile, 16 key tiles of 64.
// No running max needed (scores bounded ~|3|): plain accumulation + one
// divide at the end. Thread layout 16(ty) x 8(tx); GEMM1 micro-tile 4x8,
// GEMM2 micro-tile 4x4. K/V prefetched through registers (latency hidden
// under prior tile's GEMMs). Vs double-buffered -> only 2 barriers/iter:
//   STS K/V ; sync_A ; GEMM1 ; exp ; STS P ; sync_B ; GEMM2
// Safety: STS-K(kt) vs GEMM1(kt-1) ordered by sync_B(kt-1) (all threads past
// STS-P => past GEMM1). STS-V(kt) writes buf kt&1 while GEMM2(kt-1) reads
// buf (kt-1)&1 — disjoint. STS-P(kt) vs GEMM2(kt-1) ordered by sync_A(kt).
// Dynamic smem (52 KB > 48 KB static limit).
// ---------------------------------------------------------------------------
#define Q_OFF 0                       // float offsets into dynamic smem
#define K_OFF (32 * 68)               // 2176
#define V_OFF (K_OFF + 32 * 68)       // 4352   (two buffers of 64*36)
#define P_OFF (V_OFF + 2 * 64 * 36)   // 8960
#define SMEM_FLOATS (P_OFF + 64 * 68) // 13312 -> 53248 bytes

__global__ __launch_bounds__(128) void attn_kernel()
{
    extern __shared__ float smem[];
    float (*Qs)[68] = (float(*)[68])(smem + Q_OFF);   // [c][q-row]
    float (*Ks)[68] = (float(*)[68])(smem + K_OFF);   // [c][k-row]
    float (*Ps)[68] = (float(*)[68])(smem + P_OFF);   // [q-row][k-col]

    const int tid = threadIdx.x;
    const int tx  = tid & 7;
    const int ty  = tid >> 3;
    const int bw  = blockIdx.y;                // b*W + w
    const int h0  = blockIdx.x * BQ;

    const float* qg  = g_q + ((size_t)bw * HD + h0) * CD;
    const float* kg0 = g_k + (size_t)bw * HD * CD;
    const float* vg0 = g_v + (size_t)bw * HD * CD;

    const float inv_kd = 0.08838834764831843f;   // 1/sqrt(H/NHEAD) = 1/sqrt(128)

    // Per-thread slice of the K/V staging: 4 float4 from K, 4 from V.
    // idx = rep*128 + tid -> row r = idx>>3, quad c4 = idx&7.
    float4 kreg[4], vreg[4];

    // Prefetch tile 0
#pragma unroll
    for (int rep = 0; rep < 4; rep++) {
        int idx = rep * 128 + tid;
        int r = idx >> 3, c4 = idx & 7;
        kreg[rep] = *(const float4*)(kg0 + r * CD + c4 * 4);
        vreg[rep] = *(const float4*)(vg0 + r * CD + c4 * 4);
    }

    // Load Q tile, transposing into Qs[c][r], pre-scaled by 1/sqrt(128)
#pragma unroll
    for (int rep = 0; rep < 4; rep++) {
        int idx = rep * 128 + tid;             // 0..511
        int r = idx >> 3, c4 = idx & 7;
        float4 v = *(const float4*)(qg + r * CD + c4 * 4);
        Qs[c4 * 4 + 0][r] = v.x * inv_kd;
        Qs[c4 * 4 + 1][r] = v.y * inv_kd;
        Qs[c4 * 4 + 2][r] = v.z * inv_kd;
        Qs[c4 * 4 + 3][r] = v.w * inv_kd;
    }

    float oacc[4][4];
#pragma unroll
    for (int i = 0; i < 4; i++)
#pragma unroll
        for (int j = 0; j < 4; j++) oacc[i][j] = 0.f;
    float rsum[4] = {0.f, 0.f, 0.f, 0.f};

    for (int kt = 0; kt < HD / BK; kt++) {
        float (*Vs)[36] = (float(*)[36])(smem + V_OFF + (kt & 1) * (64 * 36));

        // Stage current tile from registers to SMEM (K transposed, V row-major)
#pragma unroll
        for (int rep = 0; rep < 4; rep++) {
            int idx = rep * 128 + tid;
            int r = idx >> 3, c4 = idx & 7;
            Ks[c4 * 4 + 0][r] = kreg[rep].x;
            Ks[c4 * 4 + 1][r] = kreg[rep].y;
            Ks[c4 * 4 + 2][r] = kreg[rep].z;
            Ks[c4 * 4 + 3][r] = kreg[rep].w;
            *(float4*)&Vs[r][c4 * 4] = vreg[rep];
        }
        __syncthreads();   // sync_A: K/V staged; also orders STS-P below vs GEMM2(kt-1)

        // Issue next tile's LDGs now; results not needed until next iteration's
        // STS, so latency hides under GEMM1 + exp + GEMM2 (~2000 FMA-cycles).
        if (kt + 1 < HD / BK) {
            const float* kg = kg0 + (size_t)(kt + 1) * BK * CD;
            const float* vg = vg0 + (size_t)(kt + 1) * BK * CD;
#pragma unroll
            for (int rep = 0; rep < 4; rep++) {
                int idx = rep * 128 + tid;
                int r = idx >> 3, c4 = idx & 7;
                kreg[rep] = *(const float4*)(kg + r * CD + c4 * 4);
                vreg[rep] = *(const float4*)(vg + r * CD + c4 * 4);
            }
        }

        // ---- GEMM1: S[4][8] = Q_tile * K_tile^T ----
        float s[4][8];
#pragma unroll
        for (int i = 0; i < 4; i++)
#pragma unroll
            for (int j = 0; j < 8; j++) s[i][j] = 0.f;

#pragma unroll
        for (int cc = 0; cc < 32; cc++) {
            float4 a  = *(const float4*)&Qs[cc][ty * 4];
            float4 b0 = *(const float4*)&Ks[cc][tx * 8];
            float4 b1 = *(const float4*)&Ks[cc][tx * 8 + 4];
            float aq[4] = {a.x, a.y, a.z, a.w};
            float bb[8] = {b0.x, b0.y, b0.z, b0.w, b1.x, b1.y, b1.z, b1.w};
#pragma unroll
            for (int i = 0; i < 4; i++)
#pragma unroll
                for (int j = 0; j < 8; j++) s[i][j] += aq[i] * bb[j];
        }

        // ---- exp, row-sum partials, stage P to SMEM ----
#pragma unroll
        for (int i = 0; i < 4; i++) {
            float e[8];
#pragma unroll
            for (int j = 0; j < 8; j++) e[j] = __expf(s[i][j]);
            rsum[i] += (e[0] + e[1] + e[2] + e[3]) + (e[4] + e[5] + e[6] + e[7]);
            *(float4*)&Ps[ty * 4 + i][tx * 8]     = make_float4(e[0], e[1], e[2], e[3]);
            *(float4*)&Ps[ty * 4 + i][tx * 8 + 4] = make_float4(e[4], e[5], e[6], e[7]);
        }
        __syncthreads();   // sync_B: P visible; all GEMM1 Ks reads done

        // ---- GEMM2: O[4][4] += P_tile * V_tile ----
#pragma unroll 4
        for (int kk = 0; kk < BK; kk += 4) {
            float p[4][4];
#pragma unroll
            for (int i = 0; i < 4; i++) {
                float4 pv = *(const float4*)&Ps[ty * 4 + i][kk];
                p[i][0] = pv.x; p[i][1] = pv.y; p[i][2] = pv.z; p[i][3] = pv.w;
            }
#pragma unroll
            for (int u = 0; u < 4; u++) {
                float4 vv = *(const float4*)&Vs[kk + u][tx * 4];
#pragma unroll
                for (int i = 0; i < 4; i++) {
                    oacc[i][0] += p[i][u] * vv.x;
                    oacc[i][1] += p[i][u] * vv.y;
                    oacc[i][2] += p[i][u] * vv.z;
                    oacc[i][3] += p[i][u] * vv.w;
                }
            }
        }
    }

    // Reduce rsum across the 8 tx lanes sharing each q-row (low 3 lane bits)
#pragma unroll
    for (int i = 0; i < 4; i++) {
        float r = rsum[i];
        r += __shfl_xor_sync(0xffffffffu, r, 1);
        r += __shfl_xor_sync(0xffffffffu, r, 2);
        r += __shfl_xor_sync(0xffffffffu, r, 4);
        rsum[i] = 1.0f / r;
    }

    float* lg = g_line + ((size_t)bw * HD + h0) * CD;
#pragma unroll
    for (int i = 0; i < 4; i++) {
        int row = ty * 4 + i;
        float4 o;
        o.x = oacc[i][0] * rsum[i];
        o.y = oacc[i][1] * rsum[i];
        o.z = oacc[i][2] * rsum[i];
        o.w = oacc[i][3] * rsum[i];
        *(float4*)&lg[row * CD + tx * 4] = o;
    }
}

// ---------------------------------------------------------------------------
// Kernel 3: epilogue — scale by sum(w_lin), add b_lin, transpose
// [B,W,H,C] -> [B,C,H,W] via SMEM tile per (b,h). Both sides coalesced.
// ---------------------------------------------------------------------------
__global__ __launch_bounds__(256) void epilogue(
    const float* __restrict__ w_lin, const float* __restrict__ b_lin,
    float* __restrict__ out)
{
    __shared__ float sh[64][33];
    int h = blockIdx.x;
    int b = blockIdx.y;
    int tid = threadIdx.x;

    float s = 0.f;
#pragma unroll
    for (int i = 0; i < NHEAD; i++) s += w_lin[i];
    float bias = b_lin[0];

#pragma unroll
    for (int rep = 0; rep < 8; rep++) {
        int idx = rep * 256 + tid;       // 0..2047
        int w = idx >> 5, c = idx & 31;
        sh[w][c] = g_line[(((size_t)b * WD + w) * HD + h) * CD + c];
    }
    __syncthreads();
#pragma unroll
    for (int rep = 0; rep < 8; rep++) {
        int idx = rep * 256 + tid;
        int c = idx >> 6, w = idx & 63;
        out[(((size_t)b * CD + c) * HD + h) * WD + w] = sh[w][c] * s + bias;
    }
}

// ---------------------------------------------------------------------------
extern "C" void kernel_launch(void* const* d_in, const int* in_sizes, int n_in,
                              void* d_out, int out_size)
{
    (void)in_sizes; (void)n_in; (void)out_size;
    const float* x     = (const float*)d_in[0];
    const float* wq    = (const float*)d_in[1];
    const float* bq    = (const float*)d_in[2];
    const float* wk    = (const float*)d_in[3];
    const float* bk    = (const float*)d_in[4];
    const float* wv    = (const float*)d_in[5];
    const float* bv    = (const float*)d_in[6];
    const float* w_lin = (const float*)d_in[7];
    const float* b_lin = (const float*)d_in[8];
    float* out = (float*)d_out;

    static bool attr_set = false;   // idempotent host-side attribute; not a stream op
    if (!attr_set) {
        cudaFuncSetAttribute(attn_kernel,
                             cudaFuncAttributeMaxDynamicSharedMemorySize,
                             SMEM_FLOATS * (int)sizeof(float));
        attr_set = true;
    }

    qkv_proj<<<(BSZ * HD * WD) / 256, 256>>>(x, wq, bq, wk, bk, wv, bv);
    attn_kernel<<<dim3(HD / BQ, BSZ * WD), 128, SMEM_FLOATS * sizeof(float)>>>();
    epilogue<<<dim3(HD, BSZ), 256>>>(w_lin, b_lin, out);
}

// round 8
// speedup vs baseline: 2.5118x; 2.5118x over previous
#include <cuda_runtime.h>
#include <cstdint>

#define BSZ   4
#define CD    32
#define HD    1024
#define WD    64
#define NHEAD 8

#define BQ 64
#define BK 64

// Scratch: q, k, v, line in [B, W, H, C] layout (per-(b,w) contiguous [H,C] matrices)
#define ELEMS (BSZ * WD * HD * CD)   // 8,388,608
__device__ float g_q[ELEMS];
__device__ float g_k[ELEMS];
__device__ float g_v[ELEMS];
__device__ float g_line[ELEMS];

// ---------------------------------------------------------------------------
// Kernel 1: fused QKV 1x1-conv projection. R4-profiled at occ 35% (69 regs,
// 3 CTAs/SM): latency-bound, DRAM only 20%. __launch_bounds__(256,4) caps at
// 64 regs -> 4 CTAs/SM; code is fully-unrolled constant indexing (no spill).
// ---------------------------------------------------------------------------
__global__ __launch_bounds__(256, 4) void qkv_proj(
    const float* __restrict__ x,
    const float* __restrict__ wq, const float* __restrict__ bq,
    const float* __restrict__ wk, const float* __restrict__ bk,
    const float* __restrict__ wv, const float* __restrict__ bv)
{
    __shared__ float shw[3][32][32];
    __shared__ float shb[3][32];
    int tid = threadIdx.x;
    for (int i = tid; i < 3 * 1024; i += 256) {
        int m = i >> 10, r = i & 1023;
        const float* ws = (m == 0) ? wq : ((m == 1) ? wk : wv);
        shw[m][r >> 5][r & 31] = ws[r];
    }
    if (tid < 96) {
        int m = tid >> 5, o = tid & 31;
        const float* bs = (m == 0) ? bq : ((m == 1) ? bk : bv);
        shb[m][o] = bs[o];
    }
    __syncthreads();

    int p = blockIdx.x * 256 + tid;         // 0 .. B*H*W-1
    int w = p & (WD - 1);
    int h = (p >> 6) & (HD - 1);
    int b = p >> 16;

    float xv[32];
    const float* xp = x + (size_t)b * CD * HD * WD + (size_t)h * WD + w;
#pragma unroll
    for (int c = 0; c < 32; c++) xv[c] = xp[(size_t)c * HD * WD];

    size_t obase = (((size_t)b * WD + w) * HD + h) * CD;

#pragma unroll 1
    for (int o4 = 0; o4 < 32; o4 += 4) {
        float aq[4], ak[4], av[4];
#pragma unroll
        for (int u = 0; u < 4; u++) {
            aq[u] = shb[0][o4 + u];
            ak[u] = shb[1][o4 + u];
            av[u] = shb[2][o4 + u];
        }
#pragma unroll
        for (int c = 0; c < 32; c++) {
            float xc = xv[c];
#pragma unroll
            for (int u = 0; u < 4; u++) {
                aq[u] += xc * shw[0][o4 + u][c];
                ak[u] += xc * shw[1][o4 + u][c];
                av[u] += xc * shw[2][o4 + u][c];
            }
        }
        *(float4*)&g_q[obase + o4] = make_float4(aq[0], aq[1], aq[2], aq[3]);
        *(float4*)&g_k[obase + o4] = make_float4(ak[0], ak[1], ak[2], ak[3]);
        *(float4*)&g_v[obase + o4] = make_float4(av[0], av[1], av[2], av[3]);
    }
}

// ---------------------------------------------------------------------------
// Kernel 2: tf32 tensor-core flash attention per (b,w) q-tile of 64 rows.
// 4 warps, warp w owns q-rows [16w,16w+16). mma.sync.m16n8k8 tf32:
//   GEMM1: S(64x64) = Q(64x32) . K^T  -> 32 MMAs/warp/iter
//   GEMM2: O(64x32) += P(64x64) . V   -> 32 MMAs/warp/iter
// Scores bounded (~|3|) => no running max. rsum accumulates the SAME
// tf32-rounded P values fed to GEMM2 (rounded word is a valid fp32), so the
// common-mode P rounding error cancels in O = (P.V)/rsum.
// Q A-fragments loaded once (k-stationary). V double-buffered: 2 bar/iter.
// Fragment maps (m16n8k8.row.col), g=lane>>2, t=lane&3:
//   A: a0=(g,t) a1=(g+8,t) a2=(g,t+4) a3=(g+8,t+4)
//   B: b0=(k=t,n=g) b1=(k=t+4,n=g)
//   C: c0=(g,2t) c1=(g,2t+1) c2=(g+8,2t) c3=(g+8,2t+1)
// Bank audit: Ks stride 36 -> LDS bank 4g+t (all distinct). Vs stride 40
// (36 would collide 2-way: 4t+g) -> bank 8t+g, all 32 distinct for b0 AND
// b1; STS.128 staging covers each bank once per phase. Ps stride 68 ->
// ap loads bank 4g+t distinct; P STS.64 has a benign 2-way.
// ---------------------------------------------------------------------------
__device__ __forceinline__ uint32_t f2tf32(float x) {
    uint32_t r;
    asm("cvt.rna.tf32.f32 %0, %1;" : "=r"(r) : "f"(x));
    return r;
}

__device__ __forceinline__ void mma_tf32(float* c, const uint32_t* a,
                                         uint32_t b0, uint32_t b1) {
    asm volatile(
        "mma.sync.aligned.m16n8k8.row.col.f32.tf32.tf32.f32 "
        "{%0,%1,%2,%3}, {%4,%5,%6,%7}, {%8,%9}, {%0,%1,%2,%3};"
        : "+f"(c[0]), "+f"(c[1]), "+f"(c[2]), "+f"(c[3])
        : "r"(a[0]), "r"(a[1]), "r"(a[2]), "r"(a[3]), "r"(b0), "r"(b1));
}

#define VST 40                           // V row stride (conflict-free: bank 8t+g)
#define QS_OFF 0                         // u32 offsets; row strides: Q/K 36, V 40, P 68
#define KS_OFF (64 * 36)                 // 2304
#define VS_OFF (KS_OFF + 64 * 36)        // 4608  (two buffers of 64*VST)
#define PS_OFF (VS_OFF + 2 * 64 * VST)   // 9728
#define SMEM_U32 (PS_OFF + 64 * 68)      // 14080 u32 = 56320 bytes

__global__ __launch_bounds__(128) void attn_kernel()
{
    extern __shared__ uint32_t smem_u[];
    uint32_t* Qs = smem_u + QS_OFF;
    uint32_t* Ks = smem_u + KS_OFF;
    uint32_t* Ps = smem_u + PS_OFF;

    const int tid  = threadIdx.x;
    const int lane = tid & 31;
    const int warp = tid >> 5;
    const int g    = lane >> 2;
    const int t    = lane & 3;
    const int r0   = warp * 16;
    const int bw   = blockIdx.y;               // b*W + w
    const int h0   = blockIdx.x * BQ;

    const float* qg  = g_q + ((size_t)bw * HD + h0) * CD;
    const float* kg0 = g_k + (size_t)bw * HD * CD;
    const float* vg0 = g_v + (size_t)bw * HD * CD;

    const float inv_kd = 0.08838834764831843f;   // 1/sqrt(H/NHEAD) = 1/sqrt(128)

    // Per-thread K/V staging slice: idx = rep*128+tid -> row r=idx>>3, quad c4=idx&7
    float4 kreg[4], vreg[4];
#pragma unroll
    for (int rep = 0; rep < 4; rep++) {
        int idx = rep * 128 + tid;
        int r = idx >> 3, c4 = idx & 7;
        kreg[rep] = *(const float4*)(kg0 + r * CD + c4 * 4);
        vreg[rep] = *(const float4*)(vg0 + r * CD + c4 * 4);
    }

    // Stage Q (tf32, pre-scaled) row-major [64][36]
#pragma unroll
    for (int rep = 0; rep < 4; rep++) {
        int idx = rep * 128 + tid;
        int r = idx >> 3, c4 = idx & 7;
        float4 v = *(const float4*)(qg + r * CD + c4 * 4);
        *(uint4*)&Qs[r * 36 + c4 * 4] =
            make_uint4(f2tf32(v.x * inv_kd), f2tf32(v.y * inv_kd),
                       f2tf32(v.z * inv_kd), f2tf32(v.w * inv_kd));
    }
    __syncthreads();

    // Q A-fragments: loaded ONCE (k-stationary across all 16 key tiles)
    uint32_t aq[4][4];
#pragma unroll
    for (int kk = 0; kk < 4; kk++) {
        aq[kk][0] = Qs[(r0 + g) * 36 + kk * 8 + t];
        aq[kk][1] = Qs[(r0 + 8 + g) * 36 + kk * 8 + t];
        aq[kk][2] = Qs[(r0 + g) * 36 + kk * 8 + 4 + t];
        aq[kk][3] = Qs[(r0 + 8 + g) * 36 + kk * 8 + 4 + t];
    }

    float o[4][4];
#pragma unroll
    for (int i = 0; i < 4; i++)
#pragma unroll
        for (int j = 0; j < 4; j++) o[i][j] = 0.f;
    float rsum0 = 0.f, rsum1 = 0.f;    // rows r0+g, r0+8+g

    for (int kt = 0; kt < HD / BK; kt++) {
        uint32_t* Vs = smem_u + VS_OFF + (kt & 1) * (64 * VST);

        // Stage K/V tiles (tf32) from prefetch registers
#pragma unroll
        for (int rep = 0; rep < 4; rep++) {
            int idx = rep * 128 + tid;
            int r = idx >> 3, c4 = idx & 7;
            *(uint4*)&Ks[r * 36 + c4 * 4] =
                make_uint4(f2tf32(kreg[rep].x), f2tf32(kreg[rep].y),
                           f2tf32(kreg[rep].z), f2tf32(kreg[rep].w));
            *(uint4*)&Vs[r * VST + c4 * 4] =
                make_uint4(f2tf32(vreg[rep].x), f2tf32(vreg[rep].y),
                           f2tf32(vreg[rep].z), f2tf32(vreg[rep].w));
        }
        __syncthreads();   // sync_A: K/V staged; orders STS-P below vs GEMM2(kt-1)

        // Prefetch next tile (latency hides under GEMM1+exp+GEMM2)
        if (kt + 1 < HD / BK) {
            const float* kg = kg0 + (size_t)(kt + 1) * BK * CD;
            const float* vg = vg0 + (size_t)(kt + 1) * BK * CD;
#pragma unroll
            for (int rep = 0; rep < 4; rep++) {
                int idx = rep * 128 + tid;
                int r = idx >> 3, c4 = idx & 7;
                kreg[rep] = *(const float4*)(kg + r * CD + c4 * 4);
                vreg[rep] = *(const float4*)(vg + r * CD + c4 * 4);
            }
        }

        // ---- GEMM1: S(16x64 per warp) = Q . K^T ----
        float c[8][4];
#pragma unroll
        for (int nt = 0; nt < 8; nt++)
#pragma unroll
            for (int j = 0; j < 4; j++) c[nt][j] = 0.f;

#pragma unroll
        for (int nt = 0; nt < 8; nt++) {
#pragma unroll
            for (int kk = 0; kk < 4; kk++) {
                uint32_t b0 = Ks[(nt * 8 + g) * 36 + kk * 8 + t];
                uint32_t b1 = Ks[(nt * 8 + g) * 36 + kk * 8 + 4 + t];
                mma_tf32(c[nt], aq[kk], b0, b1);
            }
        }

        // ---- exp -> tf32-round -> accumulate the ROUNDED values into rsum
        //      (numerator and denominator see identical P) -> stage P ----
#pragma unroll
        for (int nt = 0; nt < 8; nt++) {
            uint32_t p0 = f2tf32(__expf(c[nt][0]));
            uint32_t p1 = f2tf32(__expf(c[nt][1]));
            uint32_t p2 = f2tf32(__expf(c[nt][2]));
            uint32_t p3 = f2tf32(__expf(c[nt][3]));
            rsum0 += __uint_as_float(p0) + __uint_as_float(p1);
            rsum1 += __uint_as_float(p2) + __uint_as_float(p3);
            *(uint2*)&Ps[(r0 + g) * 68 + nt * 8 + 2 * t]     = make_uint2(p0, p1);
            *(uint2*)&Ps[(r0 + 8 + g) * 68 + nt * 8 + 2 * t] = make_uint2(p2, p3);
        }
        __syncthreads();   // sync_B: P visible; all GEMM1 Ks reads done

        // ---- GEMM2: O(16x32 per warp) += P . V ----
#pragma unroll
        for (int kk = 0; kk < 8; kk++) {
            uint32_t ap[4];
            ap[0] = Ps[(r0 + g) * 68 + kk * 8 + t];
            ap[1] = Ps[(r0 + 8 + g) * 68 + kk * 8 + t];
            ap[2] = Ps[(r0 + g) * 68 + kk * 8 + 4 + t];
            ap[3] = Ps[(r0 + 8 + g) * 68 + kk * 8 + 4 + t];
#pragma unroll
            for (int nt = 0; nt < 4; nt++) {
                uint32_t b0 = Vs[(kk * 8 + t) * VST + nt * 8 + g];
                uint32_t b1 = Vs[(kk * 8 + 4 + t) * VST + nt * 8 + g];
                mma_tf32(o[nt], ap, b0, b1);
            }
        }
    }

    // Full row sums: add the 4 lanes (t=0..3) sharing each row g
    rsum0 += __shfl_xor_sync(0xffffffffu, rsum0, 1);
    rsum0 += __shfl_xor_sync(0xffffffffu, rsum0, 2);
    rsum1 += __shfl_xor_sync(0xffffffffu, rsum1, 1);
    rsum1 += __shfl_xor_sync(0xffffffffu, rsum1, 2);
    float inv0 = 1.0f / rsum0;
    float inv1 = 1.0f / rsum1;

    // Write O: c0/c1 -> row r0+g cols (8nt+2t, +1); c2/c3 -> row r0+8+g
    float* lg = g_line + ((size_t)bw * HD + h0) * CD;
#pragma unroll
    for (int nt = 0; nt < 4; nt++) {
        *(float2*)&lg[(r0 + g) * CD + nt * 8 + 2 * t] =
            make_float2(o[nt][0] * inv0, o[nt][1] * inv0);
        *(float2*)&lg[(r0 + 8 + g) * CD + nt * 8 + 2 * t] =
            make_float2(o[nt][2] * inv1, o[nt][3] * inv1);
    }
}

// ---------------------------------------------------------------------------
// Kernel 3: epilogue — scale by sum(w_lin), add b_lin, transpose
// [B,W,H,C] -> [B,C,H,W] via SMEM tile per (b,h). Both sides coalesced.
// ---------------------------------------------------------------------------
__global__ __launch_bounds__(256) void epilogue(
    const float* __restrict__ w_lin, const float* __restrict__ b_lin,
    float* __restrict__ out)
{
    __shared__ float sh[64][33];
    int h = blockIdx.x;
    int b = blockIdx.y;
    int tid = threadIdx.x;

    float s = 0.f;
#pragma unroll
    for (int i = 0; i < NHEAD; i++) s += w_lin[i];
    float bias = b_lin[0];

#pragma unroll
    for (int rep = 0; rep < 8; rep++) {
        int idx = rep * 256 + tid;       // 0..2047
        int w = idx >> 5, c = idx & 31;
        sh[w][c] = g_line[(((size_t)b * WD + w) * HD + h) * CD + c];
    }
    __syncthreads();
#pragma unroll
    for (int rep = 0; rep < 8; rep++) {
        int idx = rep * 256 + tid;
        int c = idx >> 6, w = idx & 63;
        out[(((size_t)b * CD + c) * HD + h) * WD + w] = sh[w][c] * s + bias;
    }
}

// ---------------------------------------------------------------------------
extern "C" void kernel_launch(void* const* d_in, const int* in_sizes, int n_in,
                              void* d_out, int out_size)
{
    (void)in_sizes; (void)n_in; (void)out_size;
    const float* x     = (const float*)d_in[0];
    const float* wq    = (const float*)d_in[1];
    const float* bq    = (const float*)d_in[2];
    const float* wk    = (const float*)d_in[3];
    const float* bk    = (const float*)d_in[4];
    const float* wv    = (const float*)d_in[5];
    const float* bv    = (const float*)d_in[6];
    const float* w_lin = (const float*)d_in[7];
    const float* b_lin = (const float*)d_in[8];
    float* out = (float*)d_out;

    // Idempotent host-side attribute (not a stream op; graph-capture safe)
    cudaFuncSetAttribute(attn_kernel,
                         cudaFuncAttributeMaxDynamicSharedMemorySize,
                         SMEM_U32 * (int)sizeof(uint32_t));

    qkv_proj<<<(BSZ * HD * WD) / 256, 256>>>(x, wq, bq, wk, bk, wv, bv);
    attn_kernel<<<dim3(HD / BQ, BSZ * WD), 128, SMEM_U32 * sizeof(uint32_t)>>>();
    epilogue<<<dim3(HD, BSZ), 256>>>(w_lin, b_lin, out);
}

// round 13
// speedup vs baseline: 3.0260x; 1.2047x over previous
#include <cuda_runtime.h>
#include <cstdint>

#define BSZ   4
#define CD    32
#define HD    1024
#define WD    64
#define NHEAD 8

#define BQ 64
#define BK 64

// Scratch: q, k, v, line in [B, W, H, C] layout (per-(b,w) contiguous [H,C] matrices)
#define ELEMS (BSZ * WD * HD * CD)   // 8,388,608
__device__ float g_q[ELEMS];
__device__ float g_k[ELEMS];
__device__ float g_v[ELEMS];
__device__ float g_line[ELEMS];

// ---------------------------------------------------------------------------
// tf32 helpers (fragment maps empirically validated by the R8 attn kernel,
// rel_err 2.3e-4): m16n8k8.row.col, g=lane>>2, t=lane&3
//   A: a0=(m=g,k=t) a1=(g+8,t) a2=(g,t+4) a3=(g+8,t+4)
//   B: b0=(n=g,k=t) b1=(n=g,k=t+4)
//   C: c0=(g,2t) c1=(g,2t+1) c2=(g+8,2t) c3=(g+8,2t+1)
// ---------------------------------------------------------------------------
__device__ __forceinline__ uint32_t f2tf32(float x) {
    uint32_t r;
    asm("cvt.rna.tf32.f32 %0, %1;" : "=r"(r) : "f"(x));
    return r;
}

__device__ __forceinline__ void mma_tf32(float* c, const uint32_t* a,
                                         uint32_t b0, uint32_t b1) {
    asm volatile(
        "mma.sync.aligned.m16n8k8.row.col.f32.tf32.tf32.f32 "
        "{%0,%1,%2,%3}, {%4,%5,%6,%7}, {%8,%9}, {%0,%1,%2,%3};"
        : "+f"(c[0]), "+f"(c[1]), "+f"(c[2]), "+f"(c[3])
        : "r"(a[0]), "r"(a[1]), "r"(a[2]), "r"(a[3]), "r"(b0), "r"(b1));
}

// ---------------------------------------------------------------------------
// Kernel 1: QKV projection as ONE tf32 GEMM: D[96, pos] = W[96,32] . X[32, pos]
// (o in [0,32)=q, [32,64)=k, [64,96)=v). x's [C][HW] layout IS the col-major
// B operand. Block: 256 thr / 8 warps, pos-tile 128 (2h x 64w); warp wp owns
// n-tiles {2wp, 2wp+1}, all 6 m-tiles; 48 MMAs/warp. D staged to SMEM
// (overlaying the dead X tile after a barrier), then written as coalesced
// 128B [H,C]-rows with bias (lane -> channel). Banks: X-stage per-phase
// distinct; B-frag (8t+g) distinct; A-frag (4g+t) distinct; writeback LDS
// stride-1; D STS benign 2-way.
// ---------------------------------------------------------------------------
#define POS_TILE 128
#define WST 36
#define XST 136
#define DST 97
#define QW_OFF 0                         // W: 96*WST = 3456 u32
#define QB_OFF (96 * WST)                // bias: 96
#define QXD_OFF (QB_OFF + 96)            // union of X (32*XST=4352) and D (128*DST=12416)
#define QKV_SMEM_U32 (QXD_OFF + 128 * DST)   // 15968 u32 = 63872 B

__global__ __launch_bounds__(256) void qkv_mma(
    const float* __restrict__ x,
    const float* __restrict__ wq, const float* __restrict__ bq,
    const float* __restrict__ wk, const float* __restrict__ bk,
    const float* __restrict__ wv, const float* __restrict__ bv)
{
    extern __shared__ uint32_t sm[];
    uint32_t* Ws = sm + QW_OFF;
    float*    Bs = (float*)(sm + QB_OFF);
    uint32_t* Xs = sm + QXD_OFF;
    uint32_t* Ds = sm + QXD_OFF;         // overlays Xs (X dead after B-frag loads)

    const int tid  = threadIdx.x;
    const int lane = tid & 31;
    const int warp = tid >> 5;
    const int g    = lane >> 2;
    const int t    = lane & 3;
    const int b    = blockIdx.y;
    const int pos0 = blockIdx.x * POS_TILE;
    const size_t HW = (size_t)HD * WD;   // 65536

    // Stage W (96x32 -> tf32, row-major [o][c], stride WST)
    for (int i = tid; i < 768; i += 256) {           // 768 float4
        int o = i >> 3, q4 = i & 7;
        const float* src = (o < 32) ? (wq + o * 32)
                         : (o < 64) ? (wk + (o - 32) * 32)
                                    : (wv + (o - 64) * 32);
        float4 v = *(const float4*)(src + q4 * 4);
        *(uint4*)&Ws[o * WST + q4 * 4] =
            make_uint4(f2tf32(v.x), f2tf32(v.y), f2tf32(v.z), f2tf32(v.w));
    }
    if (tid < 96)
        Bs[tid] = (tid < 32) ? bq[tid] : (tid < 64) ? bk[tid - 32] : bv[tid - 64];

    // Stage X tile [32 c][128 pos] as tf32 (fully coalesced LDG.128 along pos)
    const float* xb = x + (size_t)b * CD * HW + pos0;
    for (int i = tid; i < 1024; i += 256) {          // 32 c * 32 float4
        int c = i >> 5, p4 = i & 31;
        float4 v = *(const float4*)(xb + (size_t)c * HW + p4 * 4);
        *(uint4*)&Xs[c * XST + p4 * 4] =
            make_uint4(f2tf32(v.x), f2tf32(v.y), f2tf32(v.z), f2tf32(v.w));
    }
    __syncthreads();

    // B-fragments for this warp's 16 positions (n-tiles 2wp, 2wp+1)
    uint32_t bf[2][4][2];
#pragma unroll
    for (int nt2 = 0; nt2 < 2; nt2++)
#pragma unroll
        for (int kk = 0; kk < 4; kk++) {
            int pcol = warp * 16 + nt2 * 8 + g;
            bf[nt2][kk][0] = Xs[(kk * 8 + t) * XST + pcol];
            bf[nt2][kk][1] = Xs[(kk * 8 + 4 + t) * XST + pcol];
        }
    __syncthreads();   // all warps done reading X; Ds may overwrite

#pragma unroll
    for (int m = 0; m < 6; m++) {
        uint32_t af[4][4];
#pragma unroll
        for (int kk = 0; kk < 4; kk++) {
            af[kk][0] = Ws[(m * 16 + g) * WST + kk * 8 + t];
            af[kk][1] = Ws[(m * 16 + 8 + g) * WST + kk * 8 + t];
            af[kk][2] = Ws[(m * 16 + g) * WST + kk * 8 + 4 + t];
            af[kk][3] = Ws[(m * 16 + 8 + g) * WST + kk * 8 + 4 + t];
        }
#pragma unroll
        for (int nt2 = 0; nt2 < 2; nt2++) {
            float C[4] = {0.f, 0.f, 0.f, 0.f};
#pragma unroll
            for (int kk = 0; kk < 4; kk++)
                mma_tf32(C, af[kk], bf[nt2][kk][0], bf[nt2][kk][1]);
            int pos = warp * 16 + nt2 * 8 + 2 * t;
            int o   = m * 16 + g;
            Ds[pos * DST + o]           = __float_as_uint(C[0]);
            Ds[(pos + 1) * DST + o]     = __float_as_uint(C[1]);
            Ds[pos * DST + o + 8]       = __float_as_uint(C[2]);
            Ds[(pos + 1) * DST + o + 8] = __float_as_uint(C[3]);
        }
    }
    __syncthreads();

    // Writeback: warp covers pos = warp + 8j; lane -> channel; 128B rows.
#pragma unroll 4
    for (int j = 0; j < 16; j++) {
        int pos = warp + j * 8;
        int gp  = pos0 + pos;
        int h   = gp >> 6;
        int w   = gp & 63;
        size_t base = (((size_t)b * WD + w) * HD + h) * CD;
        g_q[base + lane] = __uint_as_float(Ds[pos * DST + lane])      + Bs[lane];
        g_k[base + lane] = __uint_as_float(Ds[pos * DST + 32 + lane]) + Bs[32 + lane];
        g_v[base + lane] = __uint_as_float(Ds[pos * DST + 64 + lane]) + Bs[64 + lane];
    }
}

// ---------------------------------------------------------------------------
// Kernel 2: tf32 tensor-core flash attention (UNCHANGED from passing R8:
// 444 us total, rel_err 2.3e-4). No running max (scores bounded ~|3|); rsum
// uses the same tf32-rounded P as GEMM2 (self-normalizing); V double-buffered
// (2 bar/iter); Q A-fragments k-stationary.
// ---------------------------------------------------------------------------
#define VST 40                           // V row stride (conflict-free: bank 8t+g)
#define QS_OFF 0                         // u32 offsets; row strides: Q/K 36, V 40, P 68
#define KS_OFF (64 * 36)                 // 2304
#define VS_OFF (KS_OFF + 64 * 36)        // 4608  (two buffers of 64*VST)
#define PS_OFF (VS_OFF + 2 * 64 * VST)   // 9728
#define SMEM_U32 (PS_OFF + 64 * 68)      // 14080 u32 = 56320 bytes

__global__ __launch_bounds__(128) void attn_kernel()
{
    extern __shared__ uint32_t smem_u[];
    uint32_t* Qs = smem_u + QS_OFF;
    uint32_t* Ks = smem_u + KS_OFF;
    uint32_t* Ps = smem_u + PS_OFF;

    const int tid  = threadIdx.x;
    const int lane = tid & 31;
    const int warp = tid >> 5;
    const int g    = lane >> 2;
    const int t    = lane & 3;
    const int r0   = warp * 16;
    const int bw   = blockIdx.y;               // b*W + w
    const int h0   = blockIdx.x * BQ;

    const float* qg  = g_q + ((size_t)bw * HD + h0) * CD;
    const float* kg0 = g_k + (size_t)bw * HD * CD;
    const float* vg0 = g_v + (size_t)bw * HD * CD;

    const float inv_kd = 0.08838834764831843f;   // 1/sqrt(H/NHEAD) = 1/sqrt(128)

    float4 kreg[4], vreg[4];
#pragma unroll
    for (int rep = 0; rep < 4; rep++) {
        int idx = rep * 128 + tid;
        int r = idx >> 3, c4 = idx & 7;
        kreg[rep] = *(const float4*)(kg0 + r * CD + c4 * 4);
        vreg[rep] = *(const float4*)(vg0 + r * CD + c4 * 4);
    }

#pragma unroll
    for (int rep = 0; rep < 4; rep++) {
        int idx = rep * 128 + tid;
        int r = idx >> 3, c4 = idx & 7;
        float4 v = *(const float4*)(qg + r * CD + c4 * 4);
        *(uint4*)&Qs[r * 36 + c4 * 4] =
            make_uint4(f2tf32(v.x * inv_kd), f2tf32(v.y * inv_kd),
                       f2tf32(v.z * inv_kd), f2tf32(v.w * inv_kd));
    }
    __syncthreads();

    uint32_t aq[4][4];
#pragma unroll
    for (int kk = 0; kk < 4; kk++) {
        aq[kk][0] = Qs[(r0 + g) * 36 + kk * 8 + t];
        aq[kk][1] = Qs[(r0 + 8 + g) * 36 + kk * 8 + t];
        aq[kk][2] = Qs[(r0 + g) * 36 + kk * 8 + 4 + t];
        aq[kk][3] = Qs[(r0 + 8 + g) * 36 + kk * 8 + 4 + t];
    }

    float o[4][4];
#pragma unroll
    for (int i = 0; i < 4; i++)
#pragma unroll
        for (int j = 0; j < 4; j++) o[i][j] = 0.f;
    float rsum0 = 0.f, rsum1 = 0.f;

    for (int kt = 0; kt < HD / BK; kt++) {
        uint32_t* Vs = smem_u + VS_OFF + (kt & 1) * (64 * VST);

#pragma unroll
        for (int rep = 0; rep < 4; rep++) {
            int idx = rep * 128 + tid;
            int r = idx >> 3, c4 = idx & 7;
            *(uint4*)&Ks[r * 36 + c4 * 4] =
                make_uint4(f2tf32(kreg[rep].x), f2tf32(kreg[rep].y),
                           f2tf32(kreg[rep].z), f2tf32(kreg[rep].w));
            *(uint4*)&Vs[r * VST + c4 * 4] =
                make_uint4(f2tf32(vreg[rep].x), f2tf32(vreg[rep].y),
                           f2tf32(vreg[rep].z), f2tf32(vreg[rep].w));
        }
        __syncthreads();   // sync_A

        if (kt + 1 < HD / BK) {
            const float* kg = kg0 + (size_t)(kt + 1) * BK * CD;
            const float* vg = vg0 + (size_t)(kt + 1) * BK * CD;
#pragma unroll
            for (int rep = 0; rep < 4; rep++) {
                int idx = rep * 128 + tid;
                int r = idx >> 3, c4 = idx & 7;
                kreg[rep] = *(const float4*)(kg + r * CD + c4 * 4);
                vreg[rep] = *(const float4*)(vg + r * CD + c4 * 4);
            }
        }

        float c[8][4];
#pragma unroll
        for (int nt = 0; nt < 8; nt++)
#pragma unroll
            for (int j = 0; j < 4; j++) c[nt][j] = 0.f;

#pragma unroll
        for (int nt = 0; nt < 8; nt++) {
#pragma unroll
            for (int kk = 0; kk < 4; kk++) {
                uint32_t b0 = Ks[(nt * 8 + g) * 36 + kk * 8 + t];
                uint32_t b1 = Ks[(nt * 8 + g) * 36 + kk * 8 + 4 + t];
                mma_tf32(c[nt], aq[kk], b0, b1);
            }
        }

#pragma unroll
        for (int nt = 0; nt < 8; nt++) {
            uint32_t p0 = f2tf32(__expf(c[nt][0]));
            uint32_t p1 = f2tf32(__expf(c[nt][1]));
            uint32_t p2 = f2tf32(__expf(c[nt][2]));
            uint32_t p3 = f2tf32(__expf(c[nt][3]));
            rsum0 += __uint_as_float(p0) + __uint_as_float(p1);
            rsum1 += __uint_as_float(p2) + __uint_as_float(p3);
            *(uint2*)&Ps[(r0 + g) * 68 + nt * 8 + 2 * t]     = make_uint2(p0, p1);
            *(uint2*)&Ps[(r0 + 8 + g) * 68 + nt * 8 + 2 * t] = make_uint2(p2, p3);
        }
        __syncthreads();   // sync_B

#pragma unroll
        for (int kk = 0; kk < 8; kk++) {
            uint32_t ap[4];
            ap[0] = Ps[(r0 + g) * 68 + kk * 8 + t];
            ap[1] = Ps[(r0 + 8 + g) * 68 + kk * 8 + t];
            ap[2] = Ps[(r0 + g) * 68 + kk * 8 + 4 + t];
            ap[3] = Ps[(r0 + 8 + g) * 68 + kk * 8 + 4 + t];
#pragma unroll
            for (int nt = 0; nt < 4; nt++) {
                uint32_t b0 = Vs[(kk * 8 + t) * VST + nt * 8 + g];
                uint32_t b1 = Vs[(kk * 8 + 4 + t) * VST + nt * 8 + g];
                mma_tf32(o[nt], ap, b0, b1);
            }
        }
    }

    rsum0 += __shfl_xor_sync(0xffffffffu, rsum0, 1);
    rsum0 += __shfl_xor_sync(0xffffffffu, rsum0, 2);
    rsum1 += __shfl_xor_sync(0xffffffffu, rsum1, 1);
    rsum1 += __shfl_xor_sync(0xffffffffu, rsum1, 2);
    float inv0 = 1.0f / rsum0;
    float inv1 = 1.0f / rsum1;

    float* lg = g_line + ((size_t)bw * HD + h0) * CD;
#pragma unroll
    for (int nt = 0; nt < 4; nt++) {
        *(float2*)&lg[(r0 + g) * CD + nt * 8 + 2 * t] =
            make_float2(o[nt][0] * inv0, o[nt][1] * inv0);
        *(float2*)&lg[(r0 + 8 + g) * CD + nt * 8 + 2 * t] =
            make_float2(o[nt][2] * inv1, o[nt][3] * inv1);
    }
}

// ---------------------------------------------------------------------------
// Kernel 3: epilogue — scale by sum(w_lin), add b_lin, transpose
// [B,W,H,C] -> [B,C,H,W] via SMEM tile per (b,h). Both sides coalesced.
// (Fusing this into attn was evaluated and rejected: fragment->out scatter
// would cost ~8x write amplification vs the ~66MB staging it saves.)
// ---------------------------------------------------------------------------
__global__ __launch_bounds__(256) void epilogue(
    const float* __restrict__ w_lin, const float* __restrict__ b_lin,
    float* __restrict__ out)
{
    __shared__ float sh[64][33];
    int h = blockIdx.x;
    int b = blockIdx.y;
    int tid = threadIdx.x;

    float s = 0.f;
#pragma unroll
    for (int i = 0; i < NHEAD; i++) s += w_lin[i];
    float bias = b_lin[0];

#pragma unroll
    for (int rep = 0; rep < 8; rep++) {
        int idx = rep * 256 + tid;       // 0..2047
        int w = idx >> 5, c = idx & 31;
        sh[w][c] = g_line[(((size_t)b * WD + w) * HD + h) * CD + c];
    }
    __syncthreads();
#pragma unroll
    for (int rep = 0; rep < 8; rep++) {
        int idx = rep * 256 + tid;
        int c = idx >> 6, w = idx & 63;
        out[(((size_t)b * CD + c) * HD + h) * WD + w] = sh[w][c] * s + bias;
    }
}

// ---------------------------------------------------------------------------
extern "C" void kernel_launch(void* const* d_in, const int* in_sizes, int n_in,
                              void* d_out, int out_size)
{
    (void)in_sizes; (void)n_in; (void)out_size;
    const float* x     = (const float*)d_in[0];
    const float* wq    = (const float*)d_in[1];
    const float* bq    = (const float*)d_in[2];
    const float* wk    = (const float*)d_in[3];
    const float* bk    = (const float*)d_in[4];
    const float* wv    = (const float*)d_in[5];
    const float* bv    = (const float*)d_in[6];
    const float* w_lin = (const float*)d_in[7];
    const float* b_lin = (const float*)d_in[8];
    float* out = (float*)d_out;

    // Idempotent host-side attributes (not stream ops; graph-capture safe)
    cudaFuncSetAttribute(attn_kernel,
                         cudaFuncAttributeMaxDynamicSharedMemorySize,
                         SMEM_U32 * (int)sizeof(uint32_t));
    cudaFuncSetAttribute(qkv_mma,
                         cudaFuncAttributeMaxDynamicSharedMemorySize,
                         QKV_SMEM_U32 * (int)sizeof(uint32_t));

    qkv_mma<<<dim3((HD * WD) / POS_TILE, BSZ), 256,
              QKV_SMEM_U32 * sizeof(uint32_t)>>>(x, wq, bq, wk, bk, wv, bv);
    attn_kernel<<<dim3(HD / BQ, BSZ * WD), 128, SMEM_U32 * sizeof(uint32_t)>>>();
    epilogue<<<dim3(HD, BSZ), 256>>>(w_lin, b_lin, out);
}